// round 9
// baseline (speedup 1.0000x reference)
#include <cuda_runtime.h>
#include <cuda_bf16.h>
#include <cstdint>

// k_i = exp(-c_i^2), c_i = -2 + 0.25*i  (double-evaluated literals)
__constant__ float K_EXP[16] = {
    0.01831563889245985f, 0.04677062238395898f, 0.10539922456186433f, 0.20961138667265397f,
    0.36787944117144233f, 0.56978282473092210f, 0.77880078307140487f, 0.93941306281347579f,
    1.00000000000000000f, 0.93941306281347579f, 0.77880078307140487f, 0.56978282473092210f,
    0.36787944117144233f, 0.20961138667265397f, 0.10539922456186433f, 0.04677062238395898f
};

// exp(-d) rounds to 1.0f for d <= ~2^-25: tied softmax weights -> argmax picks lower index.
#define TIE_EPS 2.9802322387695312e-8f   // 2^-25

__device__ __forceinline__ void quantize_one(float xv, float& qh, float& qs, int& idx)
{
    // --- hard assignment, replicating reference fp32 boundary behavior ---
    float t = fmaf(xv, 4.0f, 8.0f);
    int lo = (int)floorf(t);
    lo = max(0, min(lo, 15));
    int hi = min(lo + 1, 15);

    float clo = fmaf((float)lo, 0.25f, -2.0f);
    float chi = fmaf((float)hi, 0.25f, -2.0f);
    float dlo = __fsub_rn(xv, clo);
    float dhi = __fsub_rn(xv, chi);
    float plo  = __fmul_rn(dlo, dlo);    // same ops/rounding as reference phi
    float phi_ = __fmul_rn(dhi, dhi);

    // hi wins only if its exp weight is strictly greater after fp32 exp rounding
    idx = (__fsub_rn(plo, phi_) > TIE_EPS) ? hi : lo;
    qh = fmaf((float)idx, 0.25f, -2.0f);

    // --- soft assignment: w_i ∝ exp(0.5*x)^i * exp(-c_i^2) ---
    float r  = __expf(0.5f * xv);
    float r2 = r * r;
    float r4 = r2 * r2;
    float r8 = r4 * r4;
    float pw[16];
    pw[0] = 1.0f; pw[1] = r;       pw[2] = r2;      pw[3] = r2 * r;
    pw[4] = r4;   pw[5] = r4 * r;  pw[6] = r4 * r2; pw[7] = r4 * (r2 * r);
#pragma unroll
    for (int i = 8; i < 16; ++i) pw[i] = pw[i - 8] * r8;

    float num = 0.0f, den = 0.0f;
#pragma unroll
    for (int i = 0; i < 16; ++i) {
        float u = K_EXP[i] * pw[i];
        den += u;
        float ci = fmaf((float)i, 0.25f, -2.0f);   // compile-time constant after unroll
        num = fmaf(ci, u, num);
    }
    qs = __fdividef(num, den);
}

__device__ __forceinline__ uint32_t smem_u32(const void* p)
{
    return (uint32_t)__cvta_generic_to_shared(p);
}

// TMA bulk store: SMEM -> GMEM, bypasses the L1tex STG wavefront path.
__device__ __forceinline__ void bulk_s2g(void* gptr, uint32_t saddr, uint32_t bytes)
{
    asm volatile("cp.async.bulk.global.shared::cta.bulk_group [%0], [%1], %2;"
                 :: "l"(gptr), "r"(saddr), "r"(bytes) : "memory");
}

// Each 256-thread block owns 256 contiguous elements (1 per thread).
// All outputs are staged in SMEM (conflict-free coalesced STS) and written by
// 4 cp.async.bulk S2G ops issued from thread 0.
__global__ void __launch_bounds__(256)
Quantize_29437705847334_kernel(
    const float* __restrict__ x,
    float* __restrict__ qbar,
    float* __restrict__ qhard,
    float* __restrict__ qsoft,
    float* __restrict__ onehot,
    int n)
{
    __shared__ float4 oh_s[1024];   // 16 KB: 256 elems x 16 floats
    __shared__ float  qh_s[256];    // 1 KB (serves both qbar and qhard)
    __shared__ float  qs_s[256];    // 1 KB

    int tid  = threadIdx.x;
    int lane = tid & 31;
    int warp = tid >> 5;
    size_t base = (size_t)blockIdx.x * 256;

    if (base + 256 <= (size_t)n) {
        float xv = __ldcs(x + base + tid);
        float qh, qs; int idx;
        quantize_one(xv, qh, qs, idx);
        qh_s[tid] = qh;
        qs_s[tid] = qs;

        // stage one_hot for this warp's 32 elements: 128 float4 slots,
        // consecutive lanes -> consecutive 16B (conflict-free STS.128)
        float4* ohw = oh_s + warp * 128;
#pragma unroll
        for (int j = 0; j < 4; ++j) {
            int g  = j * 32 + lane;           // float4 slot within warp region
            int e  = g >> 2;                  // element 0..31 within warp
            int q4 = (g & 3) << 2;            // first center of this quad
            int idx_e = __shfl_sync(0xffffffffu, idx, e);
            float4 v;
            v.x = (idx_e == q4 + 0) ? 1.0f : 0.0f;
            v.y = (idx_e == q4 + 1) ? 1.0f : 0.0f;
            v.z = (idx_e == q4 + 2) ? 1.0f : 0.0f;
            v.w = (idx_e == q4 + 3) ? 1.0f : 0.0f;
            ohw[g] = v;
        }
        __syncthreads();

        if (tid == 0) {
            asm volatile("fence.proxy.async.shared::cta;" ::: "memory");
            bulk_s2g(onehot + base * 16, smem_u32(oh_s), 16384);
            bulk_s2g(qbar  + base,       smem_u32(qh_s), 1024);
            bulk_s2g(qhard + base,       smem_u32(qh_s), 1024);
            bulk_s2g(qsoft + base,       smem_u32(qs_s), 1024);
            asm volatile("cp.async.bulk.commit_group;" ::: "memory");
            // wait only until TMA has READ the smem (writes drain independently)
            asm volatile("cp.async.bulk.wait_group.read 0;" ::: "memory");
        }
        __syncthreads();   // keep smem alive until TMA has read it
    } else {
        // scalar tail (n not a multiple of 256)
        for (size_t e = base + tid; e < (size_t)n; e += 256) {
            float qh, qs; int idx;
            quantize_one(x[e], qh, qs, idx);
            qbar[e]  = qh;
            qhard[e] = qh;
            qsoft[e] = qs;
            float* oh = onehot + e * 16;
#pragma unroll
            for (int i = 0; i < 16; ++i) oh[i] = (i == idx) ? 1.0f : 0.0f;
        }
    }
}

extern "C" void kernel_launch(void* const* d_in, const int* in_sizes, int n_in,
                              void* d_out, int out_size)
{
    const float* x = (const float*)d_in[0];
    int n = in_sizes[0];                 // 4,194,304 elements

    float* out    = (float*)d_out;
    float* qbar   = out;
    float* qhard  = out + (size_t)n;
    float* qsoft  = out + (size_t)2 * n;
    float* onehot = out + (size_t)3 * n;

    int blocks = (n + 255) / 256;
    Quantize_29437705847334_kernel<<<blocks, 256>>>(x, qbar, qhard, qsoft, onehot, n);
}

// round 10
// speedup vs baseline: 1.0583x; 1.0583x over previous
#include <cuda_runtime.h>
#include <cuda_bf16.h>

// k_i = exp(-c_i^2), c_i = -2 + 0.25*i  (double-evaluated literals)
__constant__ float K_EXP[16] = {
    0.01831563889245985f, 0.04677062238395898f, 0.10539922456186433f, 0.20961138667265397f,
    0.36787944117144233f, 0.56978282473092210f, 0.77880078307140487f, 0.93941306281347579f,
    1.00000000000000000f, 0.93941306281347579f, 0.77880078307140487f, 0.56978282473092210f,
    0.36787944117144233f, 0.20961138667265397f, 0.10539922456186433f, 0.04677062238395898f
};

// exp(-d) rounds to 1.0f for d <= ~2^-25: tied softmax weights -> argmax picks lower index.
#define TIE_EPS 2.9802322387695312e-8f   // 2^-25

__device__ __forceinline__ void quantize_one(float xv, float& qh, float& qs, int& idx)
{
    // --- hard assignment, replicating reference fp32 boundary behavior ---
    float t = fmaf(xv, 4.0f, 8.0f);
    int lo = (int)floorf(t);
    lo = max(0, min(lo, 15));
    int hi = min(lo + 1, 15);

    float clo = fmaf((float)lo, 0.25f, -2.0f);
    float chi = fmaf((float)hi, 0.25f, -2.0f);
    float dlo = __fsub_rn(xv, clo);
    float dhi = __fsub_rn(xv, chi);
    float plo  = __fmul_rn(dlo, dlo);    // same ops/rounding as reference phi
    float phi_ = __fmul_rn(dhi, dhi);

    // hi wins only if its exp weight is strictly greater after fp32 exp rounding
    idx = (__fsub_rn(plo, phi_) > TIE_EPS) ? hi : lo;
    qh = fmaf((float)idx, 0.25f, -2.0f);

    // --- soft assignment: w_i ∝ exp(0.5*x)^i * exp(-c_i^2) ---
    float r  = __expf(0.5f * xv);
    float r2 = r * r;
    float r4 = r2 * r2;
    float r8 = r4 * r4;
    float pw[16];
    pw[0] = 1.0f; pw[1] = r;       pw[2] = r2;      pw[3] = r2 * r;
    pw[4] = r4;   pw[5] = r4 * r;  pw[6] = r4 * r2; pw[7] = r4 * (r2 * r);
#pragma unroll
    for (int i = 8; i < 16; ++i) pw[i] = pw[i - 8] * r8;

    float num = 0.0f, den = 0.0f;
#pragma unroll
    for (int i = 0; i < 16; ++i) {
        float u = K_EXP[i] * pw[i];
        den += u;
        float ci = fmaf((float)i, 0.25f, -2.0f);   // compile-time constant after unroll
        num = fmaf(ci, u, num);
    }
    qs = __fdividef(num, den);
}

// Each warp handles 128 contiguous elements (4 per lane via float4).
// one_hot (128 rows x 64B = 8KB contiguous) is written with fully coalesced
// STG.128; all output stores use evict-first (streaming) hints since the data
// is write-once and would otherwise thrash L2.
__global__ void __launch_bounds__(512)
Quantize_29437705847334_kernel(
    const float* __restrict__ x,
    float* __restrict__ qbar,
    float* __restrict__ qhard,
    float* __restrict__ qsoft,
    float* __restrict__ onehot,
    int n)
{
    int lane = threadIdx.x & 31;
    int warp_id = (blockIdx.x * blockDim.x + threadIdx.x) >> 5;
    size_t base = (size_t)warp_id * 128;          // warp's first element
    if (base >= (size_t)n) return;

    if (base + 128 <= (size_t)n) {
        size_t e4 = base + (size_t)lane * 4;
        float4 xv = __ldcs(reinterpret_cast<const float4*>(x + e4));

        float qh0, qh1, qh2, qh3, qs0, qs1, qs2, qs3;
        int i0, i1, i2, i3;
        quantize_one(xv.x, qh0, qs0, i0);
        quantize_one(xv.y, qh1, qs1, i1);
        quantize_one(xv.z, qh2, qs2, i2);
        quantize_one(xv.w, qh3, qs3, i3);

        float4 qh = make_float4(qh0, qh1, qh2, qh3);
        float4 qs = make_float4(qs0, qs1, qs2, qs3);
        __stcs(reinterpret_cast<float4*>(qbar  + e4), qh);
        __stcs(reinterpret_cast<float4*>(qhard + e4), qh);
        __stcs(reinterpret_cast<float4*>(qsoft + e4), qs);

        unsigned pack = (unsigned)i0 | ((unsigned)i1 << 4) |
                        ((unsigned)i2 << 8) | ((unsigned)i3 << 12);

        float4* oh = reinterpret_cast<float4*>(onehot + base * 16);
#pragma unroll
        for (int j = 0; j < 16; ++j) {
            int g   = j * 32 + lane;          // float4 slot within warp's 8KB run
            int e   = g >> 2;                 // element 0..127 within warp
            int q4  = (g & 3) << 2;           // first center of this quad
            unsigned pk = __shfl_sync(0xffffffffu, pack, e >> 2);
            int idx_e = (int)((pk >> ((e & 3) * 4)) & 15u);
            float4 v;
            v.x = (idx_e == q4 + 0) ? 1.0f : 0.0f;
            v.y = (idx_e == q4 + 1) ? 1.0f : 0.0f;
            v.z = (idx_e == q4 + 2) ? 1.0f : 0.0f;
            v.w = (idx_e == q4 + 3) ? 1.0f : 0.0f;
            __stcs(oh + g, v);
        }
    } else {
        // scalar tail (n not a multiple of 128)
        for (size_t e = base + lane; e < (size_t)n; e += 32) {
            float qh, qs; int idx;
            quantize_one(x[e], qh, qs, idx);
            qbar[e]  = qh;
            qhard[e] = qh;
            qsoft[e] = qs;
            float* oh = onehot + e * 16;
#pragma unroll
            for (int i = 0; i < 16; ++i) oh[i] = (i == idx) ? 1.0f : 0.0f;
        }
    }
}

extern "C" void kernel_launch(void* const* d_in, const int* in_sizes, int n_in,
                              void* d_out, int out_size)
{
    const float* x = (const float*)d_in[0];
    int n = in_sizes[0];                 // 4,194,304 elements

    float* out    = (float*)d_out;
    float* qbar   = out;
    float* qhard  = out + (size_t)n;
    float* qsoft  = out + (size_t)2 * n;
    float* onehot = out + (size_t)3 * n;

    int warps = (n + 127) / 128;
    int threads = 512;                   // 16 warps/block
    int blocks = (warps * 32 + threads - 1) / threads;
    Quantize_29437705847334_kernel<<<blocks, threads>>>(x, qbar, qhard, qsoft, onehot, n);
}

// round 11
// speedup vs baseline: 1.0602x; 1.0017x over previous
#include <cuda_runtime.h>
#include <cuda_bf16.h>

// k_i = exp(-c_i^2), c_i = -2 + 0.25*i  (double-evaluated literals)
__constant__ float K_EXP[16] = {
    0.01831563889245985f, 0.04677062238395898f, 0.10539922456186433f, 0.20961138667265397f,
    0.36787944117144233f, 0.56978282473092210f, 0.77880078307140487f, 0.93941306281347579f,
    1.00000000000000000f, 0.93941306281347579f, 0.77880078307140487f, 0.56978282473092210f,
    0.36787944117144233f, 0.20961138667265397f, 0.10539922456186433f, 0.04677062238395898f
};

// exp(-d) rounds to 1.0f for d <= ~2^-25: tied softmax weights -> argmax picks lower index.
#define TIE_EPS 2.9802322387695312e-8f   // 2^-25

__device__ __forceinline__ void quantize_one(float xv, float& qh, float& qs, int& idx)
{
    // --- hard assignment, replicating reference fp32 boundary behavior ---
    float t = fmaf(xv, 4.0f, 8.0f);
    int lo = (int)floorf(t);
    lo = max(0, min(lo, 15));
    int hi = min(lo + 1, 15);

    float clo = fmaf((float)lo, 0.25f, -2.0f);
    float chi = fmaf((float)hi, 0.25f, -2.0f);
    float dlo = __fsub_rn(xv, clo);
    float dhi = __fsub_rn(xv, chi);
    float plo  = __fmul_rn(dlo, dlo);    // same ops/rounding as reference phi
    float phi_ = __fmul_rn(dhi, dhi);

    // hi wins only if its exp weight is strictly greater after fp32 exp rounding
    idx = (__fsub_rn(plo, phi_) > TIE_EPS) ? hi : lo;
    qh = fmaf((float)idx, 0.25f, -2.0f);

    // --- soft assignment: w_i ∝ exp(0.5*x)^i * exp(-c_i^2) ---
    float r  = __expf(0.5f * xv);
    float r2 = r * r;
    float r4 = r2 * r2;
    float r8 = r4 * r4;
    float pw[16];
    pw[0] = 1.0f; pw[1] = r;       pw[2] = r2;      pw[3] = r2 * r;
    pw[4] = r4;   pw[5] = r4 * r;  pw[6] = r4 * r2; pw[7] = r4 * (r2 * r);
#pragma unroll
    for (int i = 8; i < 16; ++i) pw[i] = pw[i - 8] * r8;

    float num = 0.0f, den = 0.0f;
#pragma unroll
    for (int i = 0; i < 16; ++i) {
        float u = K_EXP[i] * pw[i];
        den += u;
        float ci = fmaf((float)i, 0.25f, -2.0f);   // compile-time constant after unroll
        num = fmaf(ci, u, num);
    }
    qs = __fdividef(num, den);
}

__device__ __forceinline__ void oh_store(float4* oh, unsigned pack, int lane, int j)
{
    int g   = j * 32 + lane;          // float4 slot within warp's 8KB run
    int e   = g >> 2;                 // element 0..127 within warp
    int q4  = (g & 3) << 2;           // first center of this quad
    unsigned pk = __shfl_sync(0xffffffffu, pack, e >> 2);
    int idx_e = (int)((pk >> ((e & 3) * 4)) & 15u);
    float4 v;
    v.x = (idx_e == q4 + 0) ? 1.0f : 0.0f;
    v.y = (idx_e == q4 + 1) ? 1.0f : 0.0f;
    v.z = (idx_e == q4 + 2) ? 1.0f : 0.0f;
    v.w = (idx_e == q4 + 3) ? 1.0f : 0.0f;
    __stcs(oh + g, v);
}

// Each warp handles 128 contiguous elements (4 per lane via float4).
// one_hot (128 rows x 64B = 8KB contiguous) is written with fully coalesced
// STG.128; q-array stores are interleaved between the two halves of the
// one_hot burst to spread pressure across DRAM regions. All output stores use
// evict-first (streaming) hints (write-once data).
__global__ void __launch_bounds__(512)
Quantize_29437705847334_kernel(
    const float* __restrict__ x,
    float* __restrict__ qbar,
    float* __restrict__ qhard,
    float* __restrict__ qsoft,
    float* __restrict__ onehot,
    int n)
{
    int lane = threadIdx.x & 31;
    int warp_id = (blockIdx.x * blockDim.x + threadIdx.x) >> 5;
    size_t base = (size_t)warp_id * 128;          // warp's first element
    if (base >= (size_t)n) return;

    if (base + 128 <= (size_t)n) {
        size_t e4 = base + (size_t)lane * 4;
        float4 xv = __ldcs(reinterpret_cast<const float4*>(x + e4));

        float qh0, qh1, qh2, qh3, qs0, qs1, qs2, qs3;
        int i0, i1, i2, i3;
        quantize_one(xv.x, qh0, qs0, i0);
        quantize_one(xv.y, qh1, qs1, i1);
        quantize_one(xv.z, qh2, qs2, i2);
        quantize_one(xv.w, qh3, qs3, i3);

        float4 qh = make_float4(qh0, qh1, qh2, qh3);
        float4 qs = make_float4(qs0, qs1, qs2, qs3);

        unsigned pack = (unsigned)i0 | ((unsigned)i1 << 4) |
                        ((unsigned)i2 << 8) | ((unsigned)i3 << 12);

        float4* oh = reinterpret_cast<float4*>(onehot + base * 16);

#pragma unroll
        for (int j = 0; j < 5; ++j)  oh_store(oh, pack, lane, j);
        __stcs(reinterpret_cast<float4*>(qbar  + e4), qh);
#pragma unroll
        for (int j = 5; j < 10; ++j) oh_store(oh, pack, lane, j);
        __stcs(reinterpret_cast<float4*>(qhard + e4), qh);
#pragma unroll
        for (int j = 10; j < 15; ++j) oh_store(oh, pack, lane, j);
        __stcs(reinterpret_cast<float4*>(qsoft + e4), qs);
        oh_store(oh, pack, lane, 15);
    } else {
        // scalar tail (n not a multiple of 128)
        for (size_t e = base + lane; e < (size_t)n; e += 32) {
            float qh, qs; int idx;
            quantize_one(x[e], qh, qs, idx);
            qbar[e]  = qh;
            qhard[e] = qh;
            qsoft[e] = qs;
            float* oh = onehot + e * 16;
#pragma unroll
            for (int i = 0; i < 16; ++i) oh[i] = (i == idx) ? 1.0f : 0.0f;
        }
    }
}

extern "C" void kernel_launch(void* const* d_in, const int* in_sizes, int n_in,
                              void* d_out, int out_size)
{
    const float* x = (const float*)d_in[0];
    int n = in_sizes[0];                 // 4,194,304 elements

    float* out    = (float*)d_out;
    float* qbar   = out;
    float* qhard  = out + (size_t)n;
    float* qsoft  = out + (size_t)2 * n;
    float* onehot = out + (size_t)3 * n;

    int warps = (n + 127) / 128;
    int threads = 512;                   // 16 warps/block
    int blocks = (warps * 32 + threads - 1) / threads;
    Quantize_29437705847334_kernel<<<blocks, threads>>>(x, qbar, qhard, qsoft, onehot, n);
}